// round 2
// baseline (speedup 1.0000x reference)
#include <cuda_runtime.h>
#include <math.h>

#define NEGV (-1e9f)

__device__ float g_pool1[16*98*148*32];
__device__ float g_pool2[16*12*18*64];
__device__ float g_x3[16*1536];
__device__ float4 g_cand_box[76800];
__device__ float  g_cand_score[76800];
__device__ float  g_cand_area[76800];
__device__ int    g_cand_idx[76800];
__device__ int    g_cand_cls[76800];
__device__ int    g_cand_count;

__device__ __forceinline__ float sigmoidf_(float x) { return 1.f / (1.f + expf(-x)); }

// conv1 (10x10 s2) + relu + maxpool2 fused. grid(10,98,16), 256 thr.
__global__ __launch_bounds__(256) void conv1_pool_kernel(
    const float* __restrict__ img, const float* __restrict__ w1,
    const float* __restrict__ b1)
{
    __shared__ float s_w[9600];      // [ky][kx][ci][co]
    __shared__ float s_in[3*12*72];  // [ci][row][x]
    const int b = blockIdx.z, py = blockIdx.y, px0 = blockIdx.x * 16;
    const int tid = threadIdx.x, lane = tid & 31, wid = tid >> 5;

    for (int i = tid; i < 9600; i += 256) s_w[i] = w1[i];
    const int y0 = py * 4, x0 = px0 * 4;
    for (int i = tid; i < 3*12*72; i += 256) {
        int ci = i / (12*72), rj = i - ci*(12*72);
        int r = rj / 72, j = rj - r*72, x = x0 + j;
        s_in[i] = (x < 600) ? img[((b*400 + y0 + r)*600 + x)*3 + ci] : 0.f;
    }
    __syncthreads();

    float acc[2][4];
#pragma unroll
    for (int p = 0; p < 2; ++p) { acc[p][0]=acc[p][1]=acc[p][2]=acc[p][3]=0.f; }
    const int xb = wid * 8;

#pragma unroll
    for (int ky = 0; ky < 10; ++ky) {
#pragma unroll
        for (int ci = 0; ci < 3; ++ci) {
            float xr[2][16];
#pragma unroll
            for (int dy = 0; dy < 2; ++dy) {
                const float* rp = &s_in[ci*(12*72) + (ky + 2*dy)*72 + xb];
#pragma unroll
                for (int v = 0; v < 4; ++v) {
                    float4 tv = *(const float4*)(rp + v*4);
                    xr[dy][v*4+0]=tv.x; xr[dy][v*4+1]=tv.y; xr[dy][v*4+2]=tv.z; xr[dy][v*4+3]=tv.w;
                }
            }
#pragma unroll
            for (int kx = 0; kx < 10; ++kx) {
                float wv = s_w[((ky*10 + kx)*3 + ci)*32 + lane];
#pragma unroll
                for (int p = 0; p < 2; ++p)
#pragma unroll
                    for (int dy = 0; dy < 2; ++dy)
#pragma unroll
                        for (int dx = 0; dx < 2; ++dx)
                            acc[p][dy*2+dx] = fmaf(xr[dy][4*p + 2*dx + kx], wv, acc[p][dy*2+dx]);
            }
        }
    }
    float bias = b1[lane];
#pragma unroll
    for (int p = 0; p < 2; ++p) {
        int px = px0 + wid*2 + p;
        if (px < 148) {
            float m = fmaxf(fmaxf(acc[p][0], acc[p][1]), fmaxf(acc[p][2], acc[p][3]));
            g_pool1[((b*98 + py)*148 + px)*32 + lane] = fmaxf(m + bias, 0.f);
        }
    }
}

// conv2 (4x4 s4) + relu + maxpool2. grid(18,12,16), 64 thr (= out ch)
__global__ __launch_bounds__(64) void conv2_pool_kernel(
    const float* __restrict__ w2, const float* __restrict__ b2)
{
    __shared__ float s_in[8*8*32];
    const int b = blockIdx.z, py = blockIdx.y, px = blockIdx.x;
    const int tid = threadIdx.x;
    const int y0 = py*8, x0 = px*8;
    for (int i = tid; i < 2048; i += 64) {
        int ci = i & 31, cx = (i >> 5) & 7, r = i >> 8;
        s_in[i] = g_pool1[((b*98 + y0 + r)*148 + x0 + cx)*32 + ci];
    }
    __syncthreads();
    float acc[4] = {0.f,0.f,0.f,0.f};
#pragma unroll
    for (int ky = 0; ky < 4; ++ky)
#pragma unroll
        for (int kx = 0; kx < 4; ++kx)
#pragma unroll 8
            for (int ci = 0; ci < 32; ++ci) {
                float wv = __ldg(&w2[((ky*4 + kx)*32 + ci)*64 + tid]);
#pragma unroll
                for (int dy = 0; dy < 2; ++dy)
#pragma unroll
                    for (int dx = 0; dx < 2; ++dx)
                        acc[dy*2+dx] = fmaf(s_in[((4*dy+ky)*8 + (4*dx+kx))*32 + ci], wv, acc[dy*2+dx]);
            }
    float m = fmaxf(fmaxf(acc[0], acc[1]), fmaxf(acc[2], acc[3]));
    g_pool2[((b*12 + py)*18 + px)*64 + tid] = fmaxf(m + b2[tid], 0.f);
}

// conv3 (4x4 s4) + relu. grid(4,3,16), 128 thr (= out ch)
__global__ __launch_bounds__(128) void conv3_kernel(
    const float* __restrict__ w3, const float* __restrict__ b3)
{
    __shared__ float s_in[1024];
    const int b = blockIdx.z, oy = blockIdx.y, ox = blockIdx.x;
    const int tid = threadIdx.x;
    for (int i = tid; i < 1024; i += 128) {
        int ci = i & 63, cx = (i >> 6) & 3, r = i >> 8;
        s_in[i] = g_pool2[((b*12 + oy*4 + r)*18 + ox*4 + cx)*64 + ci];
    }
    __syncthreads();
    float acc = 0.f;
    for (int i = 0; i < 1024; ++i)
        acc = fmaf(s_in[i], __ldg(&w3[i*128 + tid]), acc);
    g_x3[b*1536 + (oy*4 + ox)*128 + tid] = fmaxf(acc + b3[tid], 0.f);
}

// dense [16,1536]@[1536,48000] + relu. grid 188, 128 thr; 2 cols x 16 batch / thr
__global__ __launch_bounds__(128) void dense_kernel(
    const float* __restrict__ wd, const float* __restrict__ bd,
    float* __restrict__ out)
{
    const int t = threadIdx.x;
    const int n1 = blockIdx.x * 256 + t, n2 = n1 + 128;
    const bool v2 = (n2 < 48000);
    float acc1[16], acc2[16];
#pragma unroll
    for (int b = 0; b < 16; ++b) { acc1[b]=0.f; acc2[b]=0.f; }
    for (int k = 0; k < 1536; k += 4) {
        float wa[4], wb[4];
#pragma unroll
        for (int j = 0; j < 4; ++j) {
            wa[j] = wd[(k+j)*48000 + n1];
            wb[j] = v2 ? wd[(k+j)*48000 + n2] : 0.f;
        }
#pragma unroll
        for (int b = 0; b < 16; ++b) {
            float4 xv = *(const float4*)&g_x3[b*1536 + k];
            acc1[b] = fmaf(xv.w, wa[3], fmaf(xv.z, wa[2], fmaf(xv.y, wa[1], fmaf(xv.x, wa[0], acc1[b]))));
            acc2[b] = fmaf(xv.w, wb[3], fmaf(xv.z, wb[2], fmaf(xv.y, wb[1], fmaf(xv.x, wb[0], acc2[b]))));
        }
    }
    float bb1 = bd[n1];
#pragma unroll
    for (int b = 0; b < 16; ++b) out[b*48000 + n1] = fmaxf(acc1[b] + bb1, 0.f);
    if (v2) {
        float bb2 = bd[n2];
#pragma unroll
        for (int b = 0; b < 16; ++b) out[b*48000 + n2] = fmaxf(acc2[b] + bb2, 0.f);
    }
}

__global__ void reset_kernel() { g_cand_count = 0; }

// decode (faithful flat reshapes) + threshold + warp-aggregated compaction
__global__ __launch_bounds__(256) void transform_kernel(const float* __restrict__ p)
{
    const int j = blockIdx.x * 256 + threadIdx.x;   // flat [B,GY,GX,2]
    const int lane = threadIdx.x & 31;

    float center[2], wh[2];
#pragma unroll
    for (int c = 0; c < 2; ++c) {
        int f = 2*j + c;
        int sa = f / 76800;  int r  = f - sa*76800;
        int sb = r / 4800;   int r2 = r - sb*4800;
        int sgy = r2 / 120;  int r3 = r2 - sgy*120;
        int sgx = r3 >> 1;   int sc = r3 & 1;
        const float* pc = p + ((sb*40 + sgy)*60 + sgx)*20;
        int off = sa ? 10 : 0;
        center[c] = sigmoidf_(pc[off + sc]) + (sc == 0 ? (float)sgx : (float)sgy);
        float anch = (sgx >= 30) ? (sc == 0 ? 0.5f : 1.0f) : (sc == 0 ? 1.0f : 0.5f);
        wh[c] = expf(pc[off + 2 + sc]) * anch;
    }
    int sa = j / 38400;  int r = j - sa*38400;
    int sb = r / 2400;   int rr = r - sb*2400;
    int sgy = rr / 60;   int sgx = rr - sgy*60;
    float obj = sigmoidf_(p[((sb*40 + sgy)*60 + sgx)*20 + (sa ? 14 : 4)]);

    float best = -1.f; int bcls = 0;
#pragma unroll
    for (int c5 = 0; c5 < 5; ++c5) {
        int g = 5*j + c5;
        int ta = g / 192000;  int q  = g - ta*192000;
        int tb = q / 12000;   int q2 = q - tb*12000;
        int tgy = q2 / 300;   int q3 = q2 - tgy*300;
        int tgx = q3 / 5;     int tc = q3 - tgx*5;
        float cl = sigmoidf_(p[((tb*40 + tgy)*60 + tgx)*20 + (ta ? 15 : 5) + tc]);
        float s = obj * cl;
        if (s > best) { best = s; bcls = c5; }   // first-max tie-break
    }

    bool keep = (best >= 0.3f);
    unsigned m = __ballot_sync(0xffffffffu, keep);
    if (keep) {
        int leader = __ffs(m) - 1;
        int base = 0;
        if (lane == leader) base = atomicAdd(&g_cand_count, __popc(m));
        base = __shfl_sync(m, base, leader);
        int pos = base + __popc(m & ((1u << lane) - 1u));
        float y1 = (center[1] - wh[1]*0.5f) * 400.f;
        float x1 = (center[0] - wh[0]*0.5f) * 600.f;
        float y2 = (center[1] + wh[1]*0.5f) * 400.f;
        float x2 = (center[0] + wh[0]*0.5f) * 600.f;
        g_cand_box[pos]   = make_float4(y1, x1, y2, x2);
        g_cand_score[pos] = best;
        g_cand_area[pos]  = fmaxf(y2 - y1, 0.f) * fmaxf(x2 - x1, 0.f);
        g_cand_idx[pos]   = j;
        g_cand_cls[pos]   = bcls;
    }
}

// NMS: single persistent block, 20 sequential selections
__global__ __launch_bounds__(1024) void nms_kernel(float* __restrict__ out)
{
    __shared__ float s_val[32];
    __shared__ int   s_idx[32], s_pos[32];
    __shared__ float s_sel[5];
    __shared__ int   s_selpos;
    const int tid = threadIdx.x;
    const int N = g_cand_count;
    float* out_boxes = out + 768000;
    float* out_scores = out + 768080;
    float* out_classes = out + 768100;

    int selPos = -1;
    float sy1=0.f, sx1=0.f, sy2=0.f, sx2=0.f, sarea=0.f;

    for (int t = 0; t < 20; ++t) {
        float best = -3e38f; int bestIdx = 0x7fffffff; int bestPos = -1;
        for (int c = tid; c < N; c += 1024) {
            float s = g_cand_score[c];
            if (selPos >= 0 && s != NEGV) {
                float4 bx = g_cand_box[c];
                float yy1 = fmaxf(sy1, bx.x), xx1 = fmaxf(sx1, bx.y);
                float yy2 = fminf(sy2, bx.z), xx2 = fminf(sx2, bx.w);
                float inter = fmaxf(yy2 - yy1, 0.f) * fmaxf(xx2 - xx1, 0.f);
                float iou = inter / (sarea + g_cand_area[c] - inter + 1e-9f);
                if (iou > 0.4f || c == selPos) { s = NEGV; g_cand_score[c] = NEGV; }
            }
            int oi = g_cand_idx[c];
            if (s > best || (s == best && oi < bestIdx)) { best = s; bestIdx = oi; bestPos = c; }
        }
#pragma unroll
        for (int off = 16; off > 0; off >>= 1) {
            float ov  = __shfl_down_sync(0xffffffffu, best, off);
            int  oidx = __shfl_down_sync(0xffffffffu, bestIdx, off);
            int  opos = __shfl_down_sync(0xffffffffu, bestPos, off);
            if (ov > best || (ov == best && oidx < bestIdx)) { best=ov; bestIdx=oidx; bestPos=opos; }
        }
        if ((tid & 31) == 0) { s_val[tid>>5]=best; s_idx[tid>>5]=bestIdx; s_pos[tid>>5]=bestPos; }
        __syncthreads();
        if (tid < 32) {
            best = s_val[tid]; bestIdx = s_idx[tid]; bestPos = s_pos[tid];
#pragma unroll
            for (int off = 16; off > 0; off >>= 1) {
                float ov  = __shfl_down_sync(0xffffffffu, best, off);
                int  oidx = __shfl_down_sync(0xffffffffu, bestIdx, off);
                int  opos = __shfl_down_sync(0xffffffffu, bestPos, off);
                if (ov > best || (ov == best && oidx < bestIdx)) { best=ov; bestIdx=oidx; bestPos=opos; }
            }
            if (tid == 0) {
                bool valid = (bestPos >= 0) && (best > NEGV * 0.5f);
                float4 bx = make_float4(0.f,0.f,0.f,0.f);
                float ar = 0.f; int cls = 0;
                if (bestPos >= 0) {
                    bx = g_cand_box[bestPos];
                    ar = g_cand_area[bestPos];
                    cls = g_cand_cls[bestPos];
                }
                out_scores[t]    = valid ? best : 0.f;
                out_boxes[4*t+0] = valid ? bx.x : 0.f;
                out_boxes[4*t+1] = valid ? bx.y : 0.f;
                out_boxes[4*t+2] = valid ? bx.z : 0.f;
                out_boxes[4*t+3] = valid ? bx.w : 0.f;
                out_classes[t]   = valid ? (float)cls : 0.f;
                s_sel[0]=bx.x; s_sel[1]=bx.y; s_sel[2]=bx.z; s_sel[3]=bx.w; s_sel[4]=ar;
                s_selpos = bestPos;
            }
        }
        __syncthreads();
        selPos = s_selpos;
        sy1=s_sel[0]; sx1=s_sel[1]; sy2=s_sel[2]; sx2=s_sel[3]; sarea=s_sel[4];
        __syncthreads();
    }
}

extern "C" void kernel_launch(void* const* d_in, const int* in_sizes, int n_in,
                              void* d_out, int out_size) {
    const float* img = (const float*)d_in[0];
    const float* w1  = (const float*)d_in[1];
    const float* b1  = (const float*)d_in[2];
    const float* w2  = (const float*)d_in[3];
    const float* b2  = (const float*)d_in[4];
    const float* w3  = (const float*)d_in[5];
    const float* b3  = (const float*)d_in[6];
    const float* wd  = (const float*)d_in[7];
    const float* bd  = (const float*)d_in[8];
    float* out = (float*)d_out;

    conv1_pool_kernel<<<dim3(10, 98, 16), 256>>>(img, w1, b1);
    conv2_pool_kernel<<<dim3(18, 12, 16), 64>>>(w2, b2);
    conv3_kernel<<<dim3(4, 3, 16), 128>>>(w3, b3);
    dense_kernel<<<188, 128>>>(wd, bd, out);
    reset_kernel<<<1, 1>>>();
    transform_kernel<<<300, 256>>>(out);
    nms_kernel<<<1, 1024>>>(out);
}

// round 3
// speedup vs baseline: 1.2578x; 1.2578x over previous
#include <cuda_runtime.h>
#include <math.h>

#define NEGV (-1e9f)

__device__ float g_pool1[16*98*148*32];
__device__ float g_pool2[16*12*18*64];
__device__ float g_x3[16*1536];
__device__ float g_part[2*16*48000];
__device__ float4 g_cand_box[76800];
__device__ float  g_cand_score[76800];
__device__ float  g_cand_area[76800];
__device__ int    g_cand_idx[76800];
__device__ int    g_cand_cls[76800];
__device__ int    g_cand_count;

__device__ __forceinline__ float sigmoidf_(float x) { return 1.f / (1.f + expf(-x)); }

// conv1 (10x10 s2) + relu + maxpool2 fused. grid(10,98,16), 256 thr.
__global__ __launch_bounds__(256) void conv1_pool_kernel(
    const float* __restrict__ img, const float* __restrict__ w1,
    const float* __restrict__ b1)
{
    __shared__ float s_w[9600];      // [ky][kx][ci][co]
    __shared__ float s_in[3*12*72];  // [ci][row][x]
    const int b = blockIdx.z, py = blockIdx.y, px0 = blockIdx.x * 16;
    const int tid = threadIdx.x, lane = tid & 31, wid = tid >> 5;

    for (int i = tid; i < 9600; i += 256) s_w[i] = w1[i];
    const int y0 = py * 4, x0 = px0 * 4;
    for (int i = tid; i < 3*12*72; i += 256) {
        int ci = i / (12*72), rj = i - ci*(12*72);
        int r = rj / 72, j = rj - r*72, x = x0 + j;
        s_in[i] = (x < 600) ? img[((b*400 + y0 + r)*600 + x)*3 + ci] : 0.f;
    }
    __syncthreads();

    float acc[2][4];
#pragma unroll
    for (int p = 0; p < 2; ++p) { acc[p][0]=acc[p][1]=acc[p][2]=acc[p][3]=0.f; }
    const int xb = wid * 8;

#pragma unroll
    for (int ky = 0; ky < 10; ++ky) {
#pragma unroll
        for (int ci = 0; ci < 3; ++ci) {
            float xr[2][16];
#pragma unroll
            for (int dy = 0; dy < 2; ++dy) {
                const float* rp = &s_in[ci*(12*72) + (ky + 2*dy)*72 + xb];
#pragma unroll
                for (int v = 0; v < 4; ++v) {
                    float4 tv = *(const float4*)(rp + v*4);
                    xr[dy][v*4+0]=tv.x; xr[dy][v*4+1]=tv.y; xr[dy][v*4+2]=tv.z; xr[dy][v*4+3]=tv.w;
                }
            }
#pragma unroll
            for (int kx = 0; kx < 10; ++kx) {
                float wv = s_w[((ky*10 + kx)*3 + ci)*32 + lane];
#pragma unroll
                for (int p = 0; p < 2; ++p)
#pragma unroll
                    for (int dy = 0; dy < 2; ++dy)
#pragma unroll
                        for (int dx = 0; dx < 2; ++dx)
                            acc[p][dy*2+dx] = fmaf(xr[dy][4*p + 2*dx + kx], wv, acc[p][dy*2+dx]);
            }
        }
    }
    float bias = b1[lane];
#pragma unroll
    for (int p = 0; p < 2; ++p) {
        int px = px0 + wid*2 + p;
        if (px < 148) {
            float m = fmaxf(fmaxf(acc[p][0], acc[p][1]), fmaxf(acc[p][2], acc[p][3]));
            g_pool1[((b*98 + py)*148 + px)*32 + lane] = fmaxf(m + bias, 0.f);
        }
    }
}

// conv2 (4x4 s4) + relu + maxpool2. grid(9,6,16), 256 thr = 64ch x 4 spatial
__global__ __launch_bounds__(256) void conv2_pool_kernel(
    const float* __restrict__ w2, const float* __restrict__ b2)
{
    __shared__ float s_in[16*16*32];   // [row][col][ci], 32KB
    const int b = blockIdx.z;
    const int py0 = blockIdx.y * 2, px0 = blockIdx.x * 2;
    const int tid = threadIdx.x;
    const int c = tid & 63, sp = tid >> 6;
    const int spy = sp >> 1, spx = sp & 1;
    const int y0 = py0*8, x0 = px0*8;
    for (int i = tid; i < 8192; i += 256) {
        int ci = i & 31, cx = (i >> 5) & 15, r = i >> 9;
        s_in[i] = g_pool1[((b*98 + y0 + r)*148 + x0 + cx)*32 + ci];
    }
    __syncthreads();
    const int rb = spy*8, cb = spx*8;
    float acc[4] = {0.f,0.f,0.f,0.f};
#pragma unroll
    for (int ky = 0; ky < 4; ++ky)
#pragma unroll
        for (int kx = 0; kx < 4; ++kx)
#pragma unroll 8
            for (int ci = 0; ci < 32; ++ci) {
                float wv = __ldg(&w2[((ky*4 + kx)*32 + ci)*64 + c]);
#pragma unroll
                for (int dy = 0; dy < 2; ++dy)
#pragma unroll
                    for (int dx = 0; dx < 2; ++dx)
                        acc[dy*2+dx] = fmaf(s_in[((rb + 4*dy + ky)*16 + cb + 4*dx + kx)*32 + ci], wv, acc[dy*2+dx]);
            }
    float m = fmaxf(fmaxf(acc[0], acc[1]), fmaxf(acc[2], acc[3]));
    g_pool2[((b*12 + py0 + spy)*18 + px0 + spx)*64 + c] = fmaxf(m + b2[c], 0.f);
}

// conv3 (4x4 s4) + relu. grid(4,3,16), 128 thr (= out ch)
__global__ __launch_bounds__(128) void conv3_kernel(
    const float* __restrict__ w3, const float* __restrict__ b3)
{
    __shared__ float s_in[1024];
    const int b = blockIdx.z, oy = blockIdx.y, ox = blockIdx.x;
    const int tid = threadIdx.x;
    for (int i = tid; i < 1024; i += 128) {
        int ci = i & 63, cx = (i >> 6) & 3, r = i >> 8;
        s_in[i] = g_pool2[((b*12 + oy*4 + r)*18 + ox*4 + cx)*64 + ci];
    }
    __syncthreads();
    float acc = 0.f;
    for (int i = 0; i < 1024; ++i)
        acc = fmaf(s_in[i], __ldg(&w3[i*128 + tid]), acc);
    g_x3[b*1536 + (oy*4 + ox)*128 + tid] = fmaxf(acc + b3[tid], 0.f);
}

// dense split-K: grid(188,2), 256 thr; thread = 1 col x 16 batch over 768 k
__global__ __launch_bounds__(256) void dense_kernel(const float* __restrict__ wd)
{
    __shared__ float s_x[16*768];      // 48KB: x[b][k0:k0+768]
    const int tid = threadIdx.x;
    const int kh = blockIdx.y, k0 = kh * 768;
    const int n = blockIdx.x * 256 + tid;
    for (int i = tid; i < 16*768; i += 256) {
        int b = i / 768, k = i - b*768;
        s_x[i] = g_x3[b*1536 + k0 + k];
    }
    __syncthreads();
    if (n >= 48000) return;

    float acc[16];
#pragma unroll
    for (int b = 0; b < 16; ++b) acc[b] = 0.f;

    const float* wp = wd + (size_t)k0 * 48000 + n;
    for (int kk = 0; kk < 768; kk += 8) {
        float w[8];
#pragma unroll
        for (int j = 0; j < 8; ++j) w[j] = wp[(size_t)(kk + j) * 48000];
#pragma unroll
        for (int b = 0; b < 16; ++b) {
            const float* xp = &s_x[b*768 + kk];
            float4 x0 = *(const float4*)xp;
            float4 x1 = *(const float4*)(xp + 4);
            float a = acc[b];
            a = fmaf(x0.x, w[0], a); a = fmaf(x0.y, w[1], a);
            a = fmaf(x0.z, w[2], a); a = fmaf(x0.w, w[3], a);
            a = fmaf(x1.x, w[4], a); a = fmaf(x1.y, w[5], a);
            a = fmaf(x1.z, w[6], a); a = fmaf(x1.w, w[7], a);
            acc[b] = a;
        }
    }
#pragma unroll
    for (int b = 0; b < 16; ++b)
        g_part[(kh*16 + b)*48000 + n] = acc[b];
}

// epilogue: out = relu(part0 + part1 + bd)
__global__ __launch_bounds__(256) void dense_epilogue_kernel(
    const float* __restrict__ bd, float* __restrict__ out)
{
    int i = blockIdx.x * 256 + threadIdx.x;
    if (i >= 768000) return;
    int n = i % 48000;
    int b = i / 48000;
    float v = g_part[b*48000 + n] + g_part[(16 + b)*48000 + n] + bd[n];
    out[i] = fmaxf(v, 0.f);
}

__global__ void reset_kernel() { g_cand_count = 0; }

// decode (faithful flat reshapes) + threshold + warp-aggregated compaction
__global__ __launch_bounds__(256) void transform_kernel(const float* __restrict__ p)
{
    const int j = blockIdx.x * 256 + threadIdx.x;   // flat [B,GY,GX,2]
    const int lane = threadIdx.x & 31;

    float center[2], wh[2];
#pragma unroll
    for (int c = 0; c < 2; ++c) {
        int f = 2*j + c;
        int sa = f / 76800;  int r  = f - sa*76800;
        int sb = r / 4800;   int r2 = r - sb*4800;
        int sgy = r2 / 120;  int r3 = r2 - sgy*120;
        int sgx = r3 >> 1;   int sc = r3 & 1;
        const float* pc = p + ((sb*40 + sgy)*60 + sgx)*20;
        int off = sa ? 10 : 0;
        center[c] = sigmoidf_(pc[off + sc]) + (sc == 0 ? (float)sgx : (float)sgy);
        float anch = (sgx >= 30) ? (sc == 0 ? 0.5f : 1.0f) : (sc == 0 ? 1.0f : 0.5f);
        wh[c] = expf(pc[off + 2 + sc]) * anch;
    }
    int sa = j / 38400;  int r = j - sa*38400;
    int sb = r / 2400;   int rr = r - sb*2400;
    int sgy = rr / 60;   int sgx = rr - sgy*60;
    float obj = sigmoidf_(p[((sb*40 + sgy)*60 + sgx)*20 + (sa ? 14 : 4)]);

    float best = -1.f; int bcls = 0;
#pragma unroll
    for (int c5 = 0; c5 < 5; ++c5) {
        int g = 5*j + c5;
        int ta = g / 192000;  int q  = g - ta*192000;
        int tb = q / 12000;   int q2 = q - tb*12000;
        int tgy = q2 / 300;   int q3 = q2 - tgy*300;
        int tgx = q3 / 5;     int tc = q3 - tgx*5;
        float cl = sigmoidf_(p[((tb*40 + tgy)*60 + tgx)*20 + (ta ? 15 : 5) + tc]);
        float s = obj * cl;
        if (s > best) { best = s; bcls = c5; }   // first-max tie-break
    }

    bool keep = (best >= 0.3f);
    unsigned m = __ballot_sync(0xffffffffu, keep);
    if (keep) {
        int leader = __ffs(m) - 1;
        int base = 0;
        if (lane == leader) base = atomicAdd(&g_cand_count, __popc(m));
        base = __shfl_sync(m, base, leader);
        int pos = base + __popc(m & ((1u << lane) - 1u));
        float y1 = (center[1] - wh[1]*0.5f) * 400.f;
        float x1 = (center[0] - wh[0]*0.5f) * 600.f;
        float y2 = (center[1] + wh[1]*0.5f) * 400.f;
        float x2 = (center[0] + wh[0]*0.5f) * 600.f;
        g_cand_box[pos]   = make_float4(y1, x1, y2, x2);
        g_cand_score[pos] = best;
        g_cand_area[pos]  = fmaxf(y2 - y1, 0.f) * fmaxf(x2 - x1, 0.f);
        g_cand_idx[pos]   = j;
        g_cand_cls[pos]   = bcls;
    }
}

// NMS: single persistent block, 20 sequential selections
__global__ __launch_bounds__(1024) void nms_kernel(float* __restrict__ out)
{
    __shared__ float s_val[32];
    __shared__ int   s_idx[32], s_pos[32];
    __shared__ float s_sel[5];
    __shared__ int   s_selpos;
    const int tid = threadIdx.x;
    const int N = g_cand_count;
    float* out_boxes = out + 768000;
    float* out_scores = out + 768080;
    float* out_classes = out + 768100;

    int selPos = -1;
    float sy1=0.f, sx1=0.f, sy2=0.f, sx2=0.f, sarea=0.f;

    for (int t = 0; t < 20; ++t) {
        float best = -3e38f; int bestIdx = 0x7fffffff; int bestPos = -1;
        for (int c = tid; c < N; c += 1024) {
            float s = g_cand_score[c];
            if (selPos >= 0 && s != NEGV) {
                float4 bx = g_cand_box[c];
                float yy1 = fmaxf(sy1, bx.x), xx1 = fmaxf(sx1, bx.y);
                float yy2 = fminf(sy2, bx.z), xx2 = fminf(sx2, bx.w);
                float inter = fmaxf(yy2 - yy1, 0.f) * fmaxf(xx2 - xx1, 0.f);
                float iou = inter / (sarea + g_cand_area[c] - inter + 1e-9f);
                if (iou > 0.4f || c == selPos) { s = NEGV; g_cand_score[c] = NEGV; }
            }
            int oi = g_cand_idx[c];
            if (s > best || (s == best && oi < bestIdx)) { best = s; bestIdx = oi; bestPos = c; }
        }
#pragma unroll
        for (int off = 16; off > 0; off >>= 1) {
            float ov  = __shfl_down_sync(0xffffffffu, best, off);
            int  oidx = __shfl_down_sync(0xffffffffu, bestIdx, off);
            int  opos = __shfl_down_sync(0xffffffffu, bestPos, off);
            if (ov > best || (ov == best && oidx < bestIdx)) { best=ov; bestIdx=oidx; bestPos=opos; }
        }
        if ((tid & 31) == 0) { s_val[tid>>5]=best; s_idx[tid>>5]=bestIdx; s_pos[tid>>5]=bestPos; }
        __syncthreads();
        if (tid < 32) {
            best = s_val[tid]; bestIdx = s_idx[tid]; bestPos = s_pos[tid];
#pragma unroll
            for (int off = 16; off > 0; off >>= 1) {
                float ov  = __shfl_down_sync(0xffffffffu, best, off);
                int  oidx = __shfl_down_sync(0xffffffffu, bestIdx, off);
                int  opos = __shfl_down_sync(0xffffffffu, bestPos, off);
                if (ov > best || (ov == best && oidx < bestIdx)) { best=ov; bestIdx=oidx; bestPos=opos; }
            }
            if (tid == 0) {
                bool valid = (bestPos >= 0) && (best > NEGV * 0.5f);
                float4 bx = make_float4(0.f,0.f,0.f,0.f);
                float ar = 0.f; int cls = 0;
                if (bestPos >= 0) {
                    bx = g_cand_box[bestPos];
                    ar = g_cand_area[bestPos];
                    cls = g_cand_cls[bestPos];
                }
                out_scores[t]    = valid ? best : 0.f;
                out_boxes[4*t+0] = valid ? bx.x : 0.f;
                out_boxes[4*t+1] = valid ? bx.y : 0.f;
                out_boxes[4*t+2] = valid ? bx.z : 0.f;
                out_boxes[4*t+3] = valid ? bx.w : 0.f;
                out_classes[t]   = valid ? (float)cls : 0.f;
                s_sel[0]=bx.x; s_sel[1]=bx.y; s_sel[2]=bx.z; s_sel[3]=bx.w; s_sel[4]=ar;
                s_selpos = bestPos;
            }
        }
        __syncthreads();
        selPos = s_selpos;
        sy1=s_sel[0]; sx1=s_sel[1]; sy2=s_sel[2]; sx2=s_sel[3]; sarea=s_sel[4];
        __syncthreads();
    }
}

extern "C" void kernel_launch(void* const* d_in, const int* in_sizes, int n_in,
                              void* d_out, int out_size) {
    const float* img = (const float*)d_in[0];
    const float* w1  = (const float*)d_in[1];
    const float* b1  = (const float*)d_in[2];
    const float* w2  = (const float*)d_in[3];
    const float* b2  = (const float*)d_in[4];
    const float* w3  = (const float*)d_in[5];
    const float* b3  = (const float*)d_in[6];
    const float* wd  = (const float*)d_in[7];
    const float* bd  = (const float*)d_in[8];
    float* out = (float*)d_out;

    conv1_pool_kernel<<<dim3(10, 98, 16), 256>>>(img, w1, b1);
    conv2_pool_kernel<<<dim3(9, 6, 16), 256>>>(w2, b2);
    conv3_kernel<<<dim3(4, 3, 16), 128>>>(w3, b3);
    dense_kernel<<<dim3(188, 2), 256>>>(wd);
    dense_epilogue_kernel<<<3000, 256>>>(bd, out);
    reset_kernel<<<1, 1>>>();
    transform_kernel<<<300, 256>>>(out);
    nms_kernel<<<1, 1024>>>(out);
}